// round 8
// baseline (speedup 1.0000x reference)
#include <cuda_runtime.h>

// CRF NLL: B=1024, T=512, C=53, BOS=1, EOS=2
// TIME-PARALLEL forward: each batch's recurrence split into NCH=4 chunks,
// one warp per chunk. Chunks ch>0 start from a uniform vector + BURN=12
// burn-in steps (Birkhoff contraction ~0.1/step -> direction exact to 1e-12),
// spliced exactly via log-scale bookkeeping:
//   contrib = L_end - L_bnd - log(sum p_bnd) + log(sum p_end)   (mid chunks)
//   contrib = L_end - L_bnd - log(sum p_bnd) + log(p_end . eos) (last chunk)
// Step kernel = R3's measured-best: 4-acc f32x2 dot, smem renorm every 4,
// exp-at-use, dist-4 raw emission prefetch. 64-thr blocks (2 warps).

#define Bn   1024
#define Tn   512
#define Cn   53
#define BOSi 1
#define EOSi 2
#define NCH  4
#define BURN 12

__device__ float    g_chunk[Bn * NCH];
__device__ unsigned g_ticket;   // zero-init; reset by last block each launch

typedef unsigned long long ull;

__device__ __forceinline__ ull pack2(float a, float b) {
    ull r; asm("mov.b64 %0, {%1,%2};" : "=l"(r) : "f"(a), "f"(b)); return r;
}
__device__ __forceinline__ void unpack2(ull v, float& a, float& b) {
    asm("mov.b64 {%0,%1}, %2;" : "=f"(a), "=f"(b) : "l"(v));
}
__device__ __forceinline__ void fma2(ull& acc, ull a, ull b) {
    asm("fma.rn.f32x2 %0, %1, %2, %0;" : "+l"(acc) : "l"(a), "l"(b));
}
__device__ __forceinline__ ull add2(ull a, ull b) {
    ull r; asm("add.rn.f32x2 %0, %1, %2;" : "=l"(r) : "l"(a), "l"(b)); return r;
}
__device__ __forceinline__ void lds_v2u64(unsigned addr, ull& x, ull& y) {
    asm volatile("ld.shared.v2.u64 {%0,%1}, [%2];" : "=l"(x), "=l"(y) : "r"(addr));
}

// one forward step (R3 recipe): dot, optional renorm by p[0], *exp(em), store
#define CRF_STEP(E0, E1, REN) do {                                          \
    unsigned pa_ = pbase + (unsigned)buf * 256u;                            \
    ull aA0_=0, aA1_=0, aB0_=0, aB1_=0;                                     \
    _Pragma("unroll")                                                       \
    for (int k_ = 0; k_ < 14; k_++) {                                       \
        ull x_, y_;                                                         \
        lds_v2u64(pa_ + 16u * k_, x_, y_);                                  \
        fma2(aA0_, x_, eA[2*k_]);  fma2(aA1_, y_, eA[2*k_+1]);              \
        fma2(aB0_, x_, eB[2*k_]);  fma2(aB1_, y_, eB[2*k_+1]);              \
    }                                                                       \
    float u_, v_, sA_, sB_;                                                 \
    unpack2(add2(aA0_, aA1_), u_, v_); sA_ = u_ + v_;                       \
    unpack2(add2(aB0_, aB1_), u_, v_); sB_ = u_ + v_;                       \
    float r_ = 1.0f;                                                        \
    if (REN) {                                                              \
        float s_ = prow[buf * 64];                                          \
        r_ = __fdividef(1.0f, s_);                                          \
        L += __logf(s_);                                                    \
    }                                                                       \
    float n0_ = sA_ * r_ * __expf(E0);                                      \
    float n1_ = sB_ * r_ * __expf(E1);                                      \
    buf ^= 1;                                                               \
    *(float2*)(prow + buf * 64 + 2 * lane) = make_float2(n0_, n1_);         \
    __syncwarp();                                                           \
    p0 = n0_; p1 = n1_;                                                     \
} while (0)

// burst-load 4 steps of RAW emissions (clamped row; exp applied at use)
#define LOAD4(P0A, P1A, BASEROW) do {                                       \
    _Pragma("unroll")                                                       \
    for (int j_ = 0; j_ < 4; j_++) {                                        \
        int rr_ = (BASEROW) + j_; if (rr_ > Tn - 1) rr_ = Tn - 1;           \
        const float* rp_ = emb + (size_t)rr_ * Cn;                          \
        P0A[j_] = __ldg(rp_ + c0v);                                         \
        P1A[j_] = __ldg(rp_ + c1v);                                         \
    }                                                                       \
} while (0)

// run the recurrence for t in [T0, T1) with dist-4 double-buffered prefetch
#define RUN_RANGE(T0, T1) do {                                              \
    int base_ = (T0);                                                       \
    LOAD4(xa, xb, base_);                                                   \
    for (;;) {                                                              \
        if (base_ + 4 > (T1)) break;                                        \
        LOAD4(ya, yb, base_ + 4);                                           \
        CRF_STEP(xa[0], xb[0], ((base_ + 0) & 3) == 2);                     \
        CRF_STEP(xa[1], xb[1], ((base_ + 1) & 3) == 2);                     \
        CRF_STEP(xa[2], xb[2], ((base_ + 2) & 3) == 2);                     \
        CRF_STEP(xa[3], xb[3], ((base_ + 3) & 3) == 2);                     \
        base_ += 4;                                                         \
        if (base_ + 4 > (T1)) break;                                        \
        LOAD4(xa, xb, base_ + 4);                                           \
        CRF_STEP(ya[0], yb[0], ((base_ + 0) & 3) == 2);                     \
        CRF_STEP(ya[1], yb[1], ((base_ + 1) & 3) == 2);                     \
        CRF_STEP(ya[2], yb[2], ((base_ + 2) & 3) == 2);                     \
        CRF_STEP(ya[3], yb[3], ((base_ + 3) & 3) == 2);                     \
        base_ += 4;                                                         \
    }                                                                       \
    for (int t_ = base_; t_ < (T1); t_++) {                                 \
        float e0_ = __ldg(emb + (size_t)t_ * Cn + c0v);                     \
        float e1_ = __ldg(emb + (size_t)t_ * Cn + c1v);                     \
        CRF_STEP(e0_, e1_, (t_ & 3) == 2);                                  \
    }                                                                       \
} while (0)

__global__ void __launch_bounds__(64)
crf_fwd_kernel(const float* __restrict__ em,
               const int*   __restrict__ tags,
               const float* __restrict__ mask,
               const float* __restrict__ trans,
               float* __restrict__ out)
{
    __shared__ float trs[Cn * Cn];
    __shared__ __align__(16) float p_sm[2][2][64];  // [warp][buf][slot]
    __shared__ float rsum[2];
    __shared__ int   slast;

    const int tid  = threadIdx.x;
    const int lane = tid & 31;
    const int w    = tid >> 5;
    const int b    = blockIdx.x >> 1;                     // batch
    const int ch   = ((blockIdx.x & 1) << 1) | w;         // chunk 0..3

    for (int i = tid; i < Cn * Cn; i += 64) trs[i] = trans[i];
    __syncthreads();

    const int  c0  = 2 * lane,            c1  = 2 * lane + 1;
    const bool okA = (c0 < Cn);           const bool okB = (c1 < Cn);
    const int  c0v = okA ? c0 : (Cn - 1); const int  c1v = okB ? c1 : (Cn - 1);

    const float* emb = em + (size_t)b * Tn * Cn;
    const int*   tg  = tags + b * Tn;
    float* prow = &p_sm[w][0][0];
    const unsigned pbase = (unsigned)__cvta_generic_to_shared(prow);

    // ---- sequence length = sum(mask) ----
    float ms = 0.f;
    for (int i = lane; i < Tn; i += 32) ms += mask[b * Tn + i];
#pragma unroll
    for (int off = 16; off; off >>= 1) ms += __shfl_xor_sync(~0u, ms, off);
    const int tl = (int)ms;   // steps run for t in [2, tl)

    // ---- chunk boundaries within [2, tl) ----
    const int s = 2 + ((tl - 2) * ch) / NCH;
    const int e = 2 + ((tl - 2) * (ch + 1)) / NCH;
    const int bs = (ch == 0) ? s : (s - BURN);   // s >= 2+63 for ch>0

    // ---- packed exp(transition) columns for this lane's 2 output cols ----
    ull eA[28], eB[28];
#pragma unroll
    for (int k = 0; k < 28; k++) {
        int r0 = 2 * k, r1 = 2 * k + 1;
        float a0 = (okA && r0 < Cn) ? __expf(trs[r0 * Cn + c0]) : 0.f;
        float a1 = (okA && r1 < Cn) ? __expf(trs[r1 * Cn + c0]) : 0.f;
        float b0 = (okB && r0 < Cn) ? __expf(trs[r0 * Cn + c1]) : 0.f;
        float b1 = (okB && r1 < Cn) ? __expf(trs[r1 * Cn + c1]) : 0.f;
        eA[k] = pack2(a0, a1);
        eB[k] = pack2(b0, b1);
    }

    // ---- init ----
    float p0, p1;
    if (ch == 0) {   // exact alpha_1 in prob domain
        p0 = okA ? __expf(trs[BOSi * Cn + c0] + emb[Cn + c0]) : 0.f;
        p1 = okB ? __expf(trs[BOSi * Cn + c1] + emb[Cn + c1]) : 0.f;
    } else {         // uniform (burn-in erases it to 1e-12)
        p0 = okA ? 1.0f : 0.f;
        p1 = okB ? 1.0f : 0.f;
    }
    int buf = 0;
    *(float2*)(prow + 2 * lane) = make_float2(p0, p1);
    __syncwarp();

    float L = 0.f;
    float xa[4], xb[4], ya[4], yb[4];

    // ---- burn-in (ch>0) then boundary snapshot ----
    float Lb = 0.f, logBeta = 0.f;
    if (ch != 0) {
        RUN_RANGE(bs, s);
        Lb = L;
        float beta = p0 + p1;
#pragma unroll
        for (int off = 16; off; off >>= 1) beta += __shfl_xor_sync(~0u, beta, off);
        logBeta = __logf(beta);
    }

    // ---- owned segment ----
    RUN_RANGE(s, e);

    // ---- chunk contribution ----
    float endv;
    if (ch == NCH - 1) {
        endv = p0 * __expf(trs[c0v * Cn + EOSi]) + p1 * __expf(trs[c1v * Cn + EOSi]);
    } else {
        endv = p0 + p1;
    }
#pragma unroll
    for (int off = 16; off; off >>= 1) endv += __shfl_xor_sync(~0u, endv, off);
    float contrib = L - Lb - logBeta + __logf(endv);

    // ---- gold-path score slice for [s, e) ----
    float sc = 0.f;
    for (int t = s + lane; t < e; t += 32) {
        int a = tg[t - 1], c = tg[t];
        sc += emb[(size_t)t * Cn + c] + trs[a * Cn + c];
    }
#pragma unroll
    for (int off = 16; off; off >>= 1) sc += __shfl_xor_sync(~0u, sc, off);

    if (lane == 0) {
        if (ch == 0) {
            int t1 = tg[1];
            sc += trs[BOSi * Cn + t1] + emb[Cn + t1];
        }
        if (ch == NCH - 1) {
            int lt = tg[tl];   // tags at index == length
            sc += trs[lt * Cn + EOSi];
        }
        g_chunk[(b << 2) | ch] = contrib - sc;
    }

    // ---- fused reduction: last block sums all chunk contributions ----
    __threadfence();
    __syncthreads();
    if (tid == 0) {
        unsigned tk = atomicAdd(&g_ticket, 1u);
        slast = (tk == (unsigned)(gridDim.x - 1)) ? 1 : 0;
    }
    __syncthreads();
    if (slast) {
        __threadfence();
        float acc = 0.f;
        for (int i = tid; i < Bn * NCH; i += 64) acc += __ldcg(&g_chunk[i]);
#pragma unroll
        for (int off = 16; off; off >>= 1) acc += __shfl_xor_sync(~0u, acc, off);
        if (lane == 0) rsum[w] = acc;
        __syncthreads();
        if (tid == 0) {
            out[0] = rsum[0] + rsum[1];
            g_ticket = 0;   // reset for next graph replay
        }
    }
}

extern "C" void kernel_launch(void* const* d_in, const int* in_sizes, int n_in,
                              void* d_out, int out_size)
{
    const float* em    = (const float*)d_in[0];
    const int*   tags  = (const int*)  d_in[1];
    const float* mask  = (const float*)d_in[2];
    const float* trans = (const float*)d_in[3];
    float* out = (float*)d_out;

    crf_fwd_kernel<<<(Bn * NCH) / 2, 64>>>(em, tags, mask, trans, out);
}

// round 9
// speedup vs baseline: 1.2040x; 1.2040x over previous
#include <cuda_runtime.h>

// CRF NLL: B=1024, T=512, C=53, BOS=1, EOS=2
// TIME-PARALLEL forward (NCH=4 chunks/batch, Birkhoff burn-in splice) in
// 128-THREAD blocks: one block per batch, warp w = chunk w, so warps land on
// all 4 SMSPs (SMSP = wid%4). __launch_bounds__(128,3) -> 3 blocks/SM ->
// 3 warps/SMSP on the whole chip (R3's proven depth, 2x the silicon).
// Step = R3 recipe: 4-acc f32x2 dot, renorm-by-p[0] every 4, exp-at-use,
// dist-4 raw emission prefetch. Fused last-block reduction.

#define Bn   1024
#define Tn   512
#define Cn   53
#define BOSi 1
#define EOSi 2
#define NCH  4
#define BURN 10

__device__ float    g_chunk[Bn * NCH];
__device__ unsigned g_ticket;   // zero-init; reset by last block each launch

typedef unsigned long long ull;

__device__ __forceinline__ ull pack2(float a, float b) {
    ull r; asm("mov.b64 %0, {%1,%2};" : "=l"(r) : "f"(a), "f"(b)); return r;
}
__device__ __forceinline__ void unpack2(ull v, float& a, float& b) {
    asm("mov.b64 {%0,%1}, %2;" : "=f"(a), "=f"(b) : "l"(v));
}
__device__ __forceinline__ void fma2(ull& acc, ull a, ull b) {
    asm("fma.rn.f32x2 %0, %1, %2, %0;" : "+l"(acc) : "l"(a), "l"(b));
}
__device__ __forceinline__ ull add2(ull a, ull b) {
    ull r; asm("add.rn.f32x2 %0, %1, %2;" : "=l"(r) : "l"(a), "l"(b)); return r;
}
__device__ __forceinline__ void lds_v2u64(unsigned addr, ull& x, ull& y) {
    asm volatile("ld.shared.v2.u64 {%0,%1}, [%2];" : "=l"(x), "=l"(y) : "r"(addr));
}

// one forward step (R3 recipe): dot, optional renorm by p[0], *exp(em), store
#define CRF_STEP(E0, E1, REN) do {                                          \
    unsigned pa_ = pbase + (unsigned)buf * 256u;                            \
    ull aA0_=0, aA1_=0, aB0_=0, aB1_=0;                                     \
    _Pragma("unroll")                                                       \
    for (int k_ = 0; k_ < 14; k_++) {                                       \
        ull x_, y_;                                                         \
        lds_v2u64(pa_ + 16u * k_, x_, y_);                                  \
        fma2(aA0_, x_, eA[2*k_]);  fma2(aA1_, y_, eA[2*k_+1]);              \
        fma2(aB0_, x_, eB[2*k_]);  fma2(aB1_, y_, eB[2*k_+1]);              \
    }                                                                       \
    float u_, v_, sA_, sB_;                                                 \
    unpack2(add2(aA0_, aA1_), u_, v_); sA_ = u_ + v_;                       \
    unpack2(add2(aB0_, aB1_), u_, v_); sB_ = u_ + v_;                       \
    float r_ = 1.0f;                                                        \
    if (REN) {                                                              \
        float s_ = prow[buf * 64];                                          \
        r_ = __fdividef(1.0f, s_);                                          \
        L += __logf(s_);                                                    \
    }                                                                       \
    float n0_ = sA_ * r_ * __expf(E0);                                      \
    float n1_ = sB_ * r_ * __expf(E1);                                      \
    buf ^= 1;                                                               \
    *(float2*)(prow + buf * 64 + 2 * lane) = make_float2(n0_, n1_);         \
    __syncwarp();                                                           \
    p0 = n0_; p1 = n1_;                                                     \
} while (0)

// burst-load 4 steps of RAW emissions (clamped row; exp applied at use)
#define LOAD4(P0A, P1A, BASEROW) do {                                       \
    _Pragma("unroll")                                                       \
    for (int j_ = 0; j_ < 4; j_++) {                                        \
        int rr_ = (BASEROW) + j_; if (rr_ > Tn - 1) rr_ = Tn - 1;           \
        const float* rp_ = emb + (size_t)rr_ * Cn;                          \
        P0A[j_] = __ldg(rp_ + c0v);                                         \
        P1A[j_] = __ldg(rp_ + c1v);                                         \
    }                                                                       \
} while (0)

// run the recurrence for t in [T0, T1) with dist-4 double-buffered prefetch
#define RUN_RANGE(T0, T1) do {                                              \
    int base_ = (T0);                                                       \
    LOAD4(xa, xb, base_);                                                   \
    for (;;) {                                                              \
        if (base_ + 4 > (T1)) break;                                        \
        LOAD4(ya, yb, base_ + 4);                                           \
        CRF_STEP(xa[0], xb[0], ((base_ + 0) & 3) == 2);                     \
        CRF_STEP(xa[1], xb[1], ((base_ + 1) & 3) == 2);                     \
        CRF_STEP(xa[2], xb[2], ((base_ + 2) & 3) == 2);                     \
        CRF_STEP(xa[3], xb[3], ((base_ + 3) & 3) == 2);                     \
        base_ += 4;                                                         \
        if (base_ + 4 > (T1)) break;                                        \
        LOAD4(xa, xb, base_ + 4);                                           \
        CRF_STEP(ya[0], yb[0], ((base_ + 0) & 3) == 2);                     \
        CRF_STEP(ya[1], yb[1], ((base_ + 1) & 3) == 2);                     \
        CRF_STEP(ya[2], yb[2], ((base_ + 2) & 3) == 2);                     \
        CRF_STEP(ya[3], yb[3], ((base_ + 3) & 3) == 2);                     \
        base_ += 4;                                                         \
    }                                                                       \
    for (int t_ = base_; t_ < (T1); t_++) {                                 \
        float e0_ = __ldg(emb + (size_t)t_ * Cn + c0v);                     \
        float e1_ = __ldg(emb + (size_t)t_ * Cn + c1v);                     \
        CRF_STEP(e0_, e1_, (t_ & 3) == 2);                                  \
    }                                                                       \
} while (0)

__global__ void __launch_bounds__(128, 3)
crf_fwd_kernel(const float* __restrict__ em,
               const int*   __restrict__ tags,
               const float* __restrict__ mask,
               const float* __restrict__ trans,
               float* __restrict__ out)
{
    __shared__ float trs[Cn * Cn];
    __shared__ __align__(16) float p_sm[4][2][64];  // [warp][buf][slot]
    __shared__ float rsum[4];
    __shared__ int   slast;

    const int tid  = threadIdx.x;
    const int lane = tid & 31;
    const int w    = tid >> 5;      // warp = chunk 0..3 (covers SMSP 0..3)
    const int b    = blockIdx.x;    // batch
    const int ch   = w;

    for (int i = tid; i < Cn * Cn; i += 128) trs[i] = trans[i];
    __syncthreads();

    const int  c0  = 2 * lane,            c1  = 2 * lane + 1;
    const bool okA = (c0 < Cn);           const bool okB = (c1 < Cn);
    const int  c0v = okA ? c0 : (Cn - 1); const int  c1v = okB ? c1 : (Cn - 1);

    const float* emb = em + (size_t)b * Tn * Cn;
    const int*   tg  = tags + b * Tn;
    float* prow = &p_sm[w][0][0];
    const unsigned pbase = (unsigned)__cvta_generic_to_shared(prow);

    // ---- sequence length = sum(mask) ----
    float ms = 0.f;
    for (int i = lane; i < Tn; i += 32) ms += mask[b * Tn + i];
#pragma unroll
    for (int off = 16; off; off >>= 1) ms += __shfl_xor_sync(~0u, ms, off);
    const int tl = (int)ms;   // steps run for t in [2, tl)

    // ---- chunk boundaries within [2, tl) ----
    const int s  = 2 + ((tl - 2) * ch) / NCH;
    const int e  = 2 + ((tl - 2) * (ch + 1)) / NCH;
    const int bs = (ch == 0) ? s : (s - BURN);   // s >= 2+63 for ch>0

    // ---- packed exp(transition) columns for this lane's 2 output cols ----
    ull eA[28], eB[28];
#pragma unroll
    for (int k = 0; k < 28; k++) {
        int r0 = 2 * k, r1 = 2 * k + 1;
        float a0 = (okA && r0 < Cn) ? __expf(trs[r0 * Cn + c0]) : 0.f;
        float a1 = (okA && r1 < Cn) ? __expf(trs[r1 * Cn + c0]) : 0.f;
        float b0 = (okB && r0 < Cn) ? __expf(trs[r0 * Cn + c1]) : 0.f;
        float b1 = (okB && r1 < Cn) ? __expf(trs[r1 * Cn + c1]) : 0.f;
        eA[k] = pack2(a0, a1);
        eB[k] = pack2(b0, b1);
    }

    // ---- init ----
    float p0, p1;
    if (ch == 0) {   // exact alpha_1 in prob domain
        p0 = okA ? __expf(trs[BOSi * Cn + c0] + emb[Cn + c0]) : 0.f;
        p1 = okB ? __expf(trs[BOSi * Cn + c1] + emb[Cn + c1]) : 0.f;
    } else {         // uniform (burn-in contracts it to ~1e-9 direction err)
        p0 = okA ? 1.0f : 0.f;
        p1 = okB ? 1.0f : 0.f;
    }
    int buf = 0;
    *(float2*)(prow + 2 * lane) = make_float2(p0, p1);
    __syncwarp();

    float L = 0.f;
    float xa[4], xb[4], ya[4], yb[4];

    // ---- burn-in (ch>0) then boundary snapshot ----
    float Lb = 0.f, logBeta = 0.f;
    if (ch != 0) {
        RUN_RANGE(bs, s);
        Lb = L;
        float beta = p0 + p1;
#pragma unroll
        for (int off = 16; off; off >>= 1) beta += __shfl_xor_sync(~0u, beta, off);
        logBeta = __logf(beta);
    }

    // ---- owned segment ----
    RUN_RANGE(s, e);

    // ---- chunk contribution ----
    float endv;
    if (ch == NCH - 1) {
        endv = p0 * __expf(trs[c0v * Cn + EOSi]) + p1 * __expf(trs[c1v * Cn + EOSi]);
    } else {
        endv = p0 + p1;
    }
#pragma unroll
    for (int off = 16; off; off >>= 1) endv += __shfl_xor_sync(~0u, endv, off);
    float contrib = L - Lb - logBeta + __logf(endv);

    // ---- gold-path score slice for [s, e) ----
    float sc = 0.f;
    for (int t = s + lane; t < e; t += 32) {
        int a = tg[t - 1], c = tg[t];
        sc += emb[(size_t)t * Cn + c] + trs[a * Cn + c];
    }
#pragma unroll
    for (int off = 16; off; off >>= 1) sc += __shfl_xor_sync(~0u, sc, off);

    if (lane == 0) {
        if (ch == 0) {
            int t1 = tg[1];
            sc += trs[BOSi * Cn + t1] + emb[Cn + t1];
        }
        if (ch == NCH - 1) {
            int lt = tg[tl];   // tags at index == length
            sc += trs[lt * Cn + EOSi];
        }
        g_chunk[(b << 2) | ch] = contrib - sc;
    }

    // ---- fused reduction: last block sums all chunk contributions ----
    __threadfence();
    __syncthreads();
    if (tid == 0) {
        unsigned tk = atomicAdd(&g_ticket, 1u);
        slast = (tk == (unsigned)(gridDim.x - 1)) ? 1 : 0;
    }
    __syncthreads();
    if (slast) {
        __threadfence();
        float acc = 0.f;
        for (int i = tid; i < Bn * NCH; i += 128) acc += __ldcg(&g_chunk[i]);
#pragma unroll
        for (int off = 16; off; off >>= 1) acc += __shfl_xor_sync(~0u, acc, off);
        if (lane == 0) rsum[w] = acc;
        __syncthreads();
        if (tid == 0) {
            out[0] = rsum[0] + rsum[1] + rsum[2] + rsum[3];
            g_ticket = 0;   // reset for next graph replay
        }
    }
}

extern "C" void kernel_launch(void* const* d_in, const int* in_sizes, int n_in,
                              void* d_out, int out_size)
{
    const float* em    = (const float*)d_in[0];
    const int*   tags  = (const int*)  d_in[1];
    const float* mask  = (const float*)d_in[2];
    const float* trans = (const float*)d_in[3];
    float* out = (float*)d_out;

    crf_fwd_kernel<<<Bn, 128>>>(em, tags, mask, trans, out);
}